// round 9
// baseline (speedup 1.0000x reference)
#include <cuda_runtime.h>
#include <cuda_fp16.h>

// out[b, o] = max_i min(x[b, i], W[i, o])   (fuzzy max-min composition)
// x: [1024, 512] f32, W: [512, 512] f32, out: [1024, 512] f32.
//
// R9: bucketed early-exit scan (sort-free).
//   Per row b: partition indices i into descending x-value segments via a
//   10-level threshold histogram (no sort). Scan segments in order with
//   best = max_j min(x_j, w_j,o); at 16-row checkpoints exit when
//   best >= U (U = upper bound of all remaining items' x). Sound for any
//   input; uniform data exits after ~48-64 of 512 rows (~9x less work).
//   Compute in fp16 (same numerics as the dense fp16 kernel, rel_err 1.5e-4).

#define B_DIM   1024
#define IN_F    512
#define OUT_F   512
#define THREADS 256
#define NSEG    10

// scratch: w packed-half2 [k][n/2]  (512 KB, L2-resident)
__device__ __align__(16) unsigned g_wh[IN_F * OUT_F / 2];

// segment lower bounds, descending (exactly representable in fp16:
// monotone f32->f16 rounding then preserves "x < TH  =>  half(x) <= TH")
__constant__ float TH32[NSEG - 1] = {
    0.96875f, 0.9375f, 0.90625f, 0.875f, 0.8125f,
    0.75f, 0.625f, 0.5f, 0.25f
};

// ---------------- prepass: w f32 -> packed half2 [k][n/2] ----------------
__global__ __launch_bounds__(256)
void prep_w(const float* __restrict__ w)
{
    const int t = threadIdx.x;
    const int f4base = blockIdx.x * 512 + t * 2;
    float4 a = ((const float4*)w)[f4base];
    float4 b = ((const float4*)w)[f4base + 1];
    __half2 h0 = __floats2half2_rn(a.x, a.y);
    __half2 h1 = __floats2half2_rn(a.z, a.w);
    __half2 h2 = __floats2half2_rn(b.x, b.y);
    __half2 h3 = __floats2half2_rn(b.z, b.w);
    ((uint4*)g_wh)[blockIdx.x * 256 + t] = make_uint4(
        *(unsigned*)&h0, *(unsigned*)&h1, *(unsigned*)&h2, *(unsigned*)&h3);
}

// ---------------- main: bucket + early-exit scan ----------------
// One block per batch row b; thread t owns outputs o = 2t, 2t+1.
__global__ __launch_bounds__(THREADS)
void maxmin_bucket(const float* __restrict__ x, float* __restrict__ out)
{
    __shared__ int            hist[NSEG];
    __shared__ int            off[NSEG];
    __shared__ unsigned short pidx[IN_F];   // permuted row indices
    __shared__ unsigned       pxd[IN_F];    // dup-half2 of x, permuted
    __shared__ __half2        ubh[32];      // per-checkpoint remaining upper bound

    const int t = threadIdx.x;
    const int b = blockIdx.x;

    if (t < NSEG) hist[t] = 0;
    __syncthreads();

    // ---- segment ids + histogram (each thread handles 2 i's) ----
    float xv[2];
    int   sg[2];
#pragma unroll
    for (int u = 0; u < 2; u++) {
        float v = x[b * IN_F + t + u * THREADS];
        xv[u] = v;
        int s = 0;
#pragma unroll
        for (int q = 0; q < NSEG - 1; q++) s += (v < TH32[q]) ? 1 : 0;
        sg[u] = s;
        atomicAdd(&hist[s], 1);
    }
    __syncthreads();

    // ---- prefix + checkpoint upper bounds (thread 0, trivial sizes) ----
    if (t == 0) {
        int pref[NSEG + 1];
        pref[0] = 0;
        for (int s = 0; s < NSEG; s++) { pref[s + 1] = pref[s] + hist[s]; off[s] = pref[s]; }
        for (int cp = 0; cp < 32; cp++) {
            int j = (cp + 1) * 16;
            float U = 2.0f;                       // unreachable for fp16 < 1
            if (j < IN_F) {
                int s = 0;
                while (!(j < pref[s + 1])) s++;   // segment containing item j
                U = (s == 0) ? 2.0f : TH32[s - 1];
            }
            ubh[cp] = __float2half2_rn(U);
        }
    }
    __syncthreads();

    // ---- scatter into permuted order (order within segment arbitrary) ----
#pragma unroll
    for (int u = 0; u < 2; u++) {
        int pos = atomicAdd(&off[sg[u]], 1);
        pidx[pos] = (unsigned short)(t + u * THREADS);
        __half2 d = __float2half2_rn(xv[u]);
        pxd[pos] = *(unsigned*)&d;
    }
    __syncthreads();

    // ---- early-exit scan: best = max_j min(x_j, w_j,o), fp16x2 ----
    __half2 best = __float2half2_rn(-65504.f);
    int j = 0;
#pragma unroll 1
    for (int chunk = 0; chunk < 32; chunk++) {
#pragma unroll
        for (int u2 = 0; u2 < 16; u2++) {        // 16 front-batched LDGs (MLP)
            int idx = pidx[j + u2];               // warp-uniform smem broadcast
            unsigned wv = g_wh[idx * (OUT_F / 2) + t];  // coalesced 128B/warp
            unsigned xd = pxd[j + u2];
            best = __hmax2(best, __hmin2(*(__half2*)&xd, *(__half2*)&wv));
        }
        j += 16;
        if (j >= IN_F) break;
        // all remaining x < U: any future candidate <= x_future < U <= best
        if (__all_sync(0xFFFFFFFFu, __hbge2(best, ubh[chunk]))) break;
    }

    // ---- store (f32 pair per thread, coalesced) ----
    float2 o = __half22float2(best);
    *(float2*)(out + b * OUT_F + t * 2) = o;
}

extern "C" void kernel_launch(void* const* d_in, const int* in_sizes, int n_in,
                              void* d_out, int out_size)
{
    const float* x = (const float*)d_in[0];   // [1024, 512]
    const float* w = (const float*)d_in[1];   // [512, 512]
    float* out = (float*)d_out;               // [1024, 512]

    prep_w<<<128, 256>>>(w);
    maxmin_bucket<<<B_DIM, THREADS>>>(x, out);
}

// round 10
// speedup vs baseline: 1.1000x; 1.1000x over previous
#include <cuda_runtime.h>
#include <cuda_fp16.h>
#include <math_constants.h>

// out[b, o] = max_i min(x[b, i], W[i, o])   (fuzzy max-min composition)
// x: [1024, 512] f32, W: [512, 512] f32, out: [1024, 512] f32.
//
// R10: bucketed early-exit, overhead-stripped.
//  - warp-parallel prefix + checkpoint bounds (R9 had a serial thread-0 loop)
//  - software-pipelined scan: chunk c+1's W loads issue before chunk c's
//    accumulate/exit-check (R9 exposed ~250cyc L2 latency per chunk)
//  - 4 outputs per thread (128 threads/block, uint2 W loads)
//  - checkpoint every 8 rows; provably sound exit for any input; full
//    512-row fallback if no exit. fp16 compute (rel_err ~1.5e-4).

#define B_DIM   1024
#define IN_F    512
#define OUT_F   512
#define THREADS 128
#define NSEG    10
#define CH      8            // rows per chunk
#define NCH     (IN_F / CH)  // 64 chunks

// scratch: w packed-half2 [k][n/2]  (512 KB, L2-resident)
__device__ __align__(16) unsigned g_wh[IN_F * OUT_F / 2];

// segment lower bounds, descending; all exactly representable in fp16
__constant__ float TH32[NSEG - 1] = {
    0.96875f, 0.9375f, 0.90625f, 0.875f, 0.8125f,
    0.75f, 0.625f, 0.5f, 0.25f
};

// ---------------- prepass: w f32 -> packed half2 [k][n/2] ----------------
__global__ __launch_bounds__(256)
void prep_w(const float* __restrict__ w)
{
    const int t = threadIdx.x;
    const int f4base = blockIdx.x * 512 + t * 2;
    float4 a = ((const float4*)w)[f4base];
    float4 b = ((const float4*)w)[f4base + 1];
    __half2 h0 = __floats2half2_rn(a.x, a.y);
    __half2 h1 = __floats2half2_rn(a.z, a.w);
    __half2 h2 = __floats2half2_rn(b.x, b.y);
    __half2 h3 = __floats2half2_rn(b.z, b.w);
    ((uint4*)g_wh)[blockIdx.x * 256 + t] = make_uint4(
        *(unsigned*)&h0, *(unsigned*)&h1, *(unsigned*)&h2, *(unsigned*)&h3);
}

// ---------------- main: bucket + pipelined early-exit scan ----------------
// One block per row b; thread t owns outputs o = 4t .. 4t+3.
__global__ __launch_bounds__(THREADS, 6)
void maxmin_bucket(const float* __restrict__ x, float* __restrict__ out)
{
    __shared__ int     hist[NSEG];
    __shared__ int     off[NSEG];
    __shared__ int     pref[NSEG + 1];
    __shared__ __half2 ubh[NCH];      // exit bound after chunk c
    __shared__ uint2   meta[IN_F];    // {w row elem-offset, dup-half2 of x}

    const int t    = threadIdx.x;
    const int b    = blockIdx.x;
    const int lane = t & 31;

    if (t < NSEG) hist[t] = 0;
    __syncthreads();

    // ---- load 4 x values (float4, coalesced), segment ids, histogram ----
    float4 xq = ((const float4*)x)[b * (IN_F / 4) + t];
    float xv[4] = {xq.x, xq.y, xq.z, xq.w};
    int   sg[4];
#pragma unroll
    for (int u = 0; u < 4; u++) {
        int s = 0;
#pragma unroll
        for (int q = 0; q < NSEG - 1; q++) s += (xv[u] < TH32[q]) ? 1 : 0;
        sg[u] = s;
        atomicAdd(&hist[s], 1);
    }
    __syncthreads();

    // ---- warp 0: parallel prefix + checkpoint bounds ----
    if (t < 32) {
        int h = (lane < NSEG) ? hist[lane] : 0;
        int v = h;
#pragma unroll
        for (int d = 1; d < 16; d <<= 1) {
            int n = __shfl_up_sync(0xFFFFFFFFu, v, d);
            if (lane >= d) v += n;
        }
        int excl = v - h;
        if (lane < NSEG) { off[lane] = excl; pref[lane] = excl; }
        if (lane == 0)   pref[NSEG] = IN_F;
        __syncwarp();
#pragma unroll
        for (int rep = 0; rep < 2; rep++) {
            int cp = lane + rep * 32;              // chunk index 0..63
            int j  = (cp + 1) * CH;                // rows consumed after chunk cp
            float U;
            if (j >= IN_F) U = CUDART_INF_F;
            else {
                int s = 0;
#pragma unroll
                for (int q = 1; q <= NSEG; q++) s += (pref[q] <= j) ? 1 : 0;
                U = (s == 0) ? CUDART_INF_F : TH32[s - 1];
            }
            ubh[cp] = __float2half2_rn(U);
        }
    }
    __syncthreads();

    // ---- scatter into segment-ordered meta ----
#pragma unroll
    for (int u = 0; u < 4; u++) {
        int pos = atomicAdd(&off[sg[u]], 1);
        int idx = t * 4 + u;                       // original row index
        __half2 d = __float2half2_rn(xv[u]);
        meta[pos] = make_uint2((unsigned)(idx * (OUT_F / 2)), *(unsigned*)&d);
    }
    __syncthreads();

    // ---- pipelined early-exit scan ----
    const int te = t * 2;                          // uint2 W offset per thread
    uint2 wbuf[2][CH];
#pragma unroll
    for (int u = 0; u < CH; u++)
        wbuf[0][u] = *(const uint2*)&g_wh[meta[u].x + te];

    __half2 best0 = __float2half2_rn(-65504.f);
    __half2 best1 = best0;

#pragma unroll 1
    for (int c = 0; c < NCH; c++) {
        const int cur = c & 1;
        if (c + 1 < NCH) {                         // prefetch next chunk's W
#pragma unroll
            for (int u = 0; u < CH; u++)
                wbuf[cur ^ 1][u] = *(const uint2*)&g_wh[meta[(c + 1) * CH + u].x + te];
        }
#pragma unroll
        for (int u = 0; u < CH; u++) {             // accumulate current chunk
            unsigned xd = meta[c * CH + u].y;      // warp-uniform broadcast
            __half2 xh = *(__half2*)&xd;
            uint2 wv = wbuf[cur][u];
            best0 = __hmax2(best0, __hmin2(xh, *(__half2*)&wv.x));
            best1 = __hmax2(best1, __hmin2(xh, *(__half2*)&wv.y));
        }
        // all remaining x < U  =>  future candidates <= U <= best: exit
        __half2 U = ubh[c];
        if (__all_sync(0xFFFFFFFFu, __hbge2(best0, U) && __hbge2(best1, U)))
            break;
    }

    // ---- store 4 outputs (float4, coalesced) ----
    float2 a = __half22float2(best0);
    float2 d = __half22float2(best1);
    *(float4*)(out + b * OUT_F + t * 4) = make_float4(a.x, a.y, d.x, d.y);
}

extern "C" void kernel_launch(void* const* d_in, const int* in_sizes, int n_in,
                              void* d_out, int out_size)
{
    const float* x = (const float*)d_in[0];   // [1024, 512]
    const float* w = (const float*)d_in[1];   // [512, 512]
    float* out = (float*)d_out;               // [1024, 512]

    prep_w<<<128, 256>>>(w);
    maxmin_bucket<<<B_DIM, THREADS>>>(x, out);
}